// round 10
// baseline (speedup 1.0000x reference)
#include <cuda_runtime.h>
#include <cuda_fp16.h>

#define N_ENT   100000
#define N_REL   16
#define DIM     64
#define N_EDGES 1600000

typedef unsigned long long ull;

// ---------------- device scratch (no allocs allowed) ----------------
__device__ __half g_proj[(size_t)N_REL * N_ENT * DIM];  // 204.8 MB, fp16
__device__ int   g_cnt[N_ENT];                          // histogram
__device__ int   g_base[N_ENT + 1];                     // CSR row offsets
__device__ int   g_cur[N_ENT];                          // scatter cursors
__device__ int   s_src[N_EDGES];                        // dst-sorted src
__device__ int   s_dst[N_EDGES];                        // dst-sorted dst
__device__ int   s_et[N_EDGES];                         // dst-sorted etype
__device__ float s_att[N_EDGES];                        // att -> softmax weight (sorted order)
__device__ float g_agg1[N_ENT * DIM];
__device__ float g_agg2[N_ENT * DIM];
__device__ float g_h1[N_ENT * DIM];                     // unnormalized layer-1 h

// ---------------- helpers ----------------
__device__ __forceinline__ float ftanh(float x) {       // MUFU.EX2 + RCP, ~1e-6 rel
    x = fminf(fmaxf(x, -15.f), 15.f);
    float e = __expf(2.f * x);
    return __fdividef(e - 1.f, e + 1.f);
}
__device__ __forceinline__ ull pack2(float lo, float hi) {
    ull r; asm("mov.b64 %0, {%1, %2};" : "=l"(r) : "f"(lo), "f"(hi)); return r;
}
__device__ __forceinline__ float2 unpack2(ull v) {
    float lo, hi; asm("mov.b64 {%0, %1}, %2;" : "=f"(lo), "=f"(hi) : "l"(v));
    return make_float2(lo, hi);
}
__device__ __forceinline__ ull ffma2(ull a, ull b, ull c) {
    ull d; asm("fma.rn.f32x2 %0, %1, %2, %3;" : "=l"(d) : "l"(a), "l"(b), "l"(c)); return d;
}

// ---------------- zero histogram ----------------
__global__ void k_zero() {
    int i = blockIdx.x * blockDim.x + threadIdx.x;
    if (i < N_ENT) g_cnt[i] = 0;
}

// ---------------- histogram of dst ----------------
__global__ void k_hist(const int* __restrict__ dst) {
    int e = blockIdx.x * blockDim.x + threadIdx.x;
    if (e < N_EDGES) atomicAdd(&g_cnt[dst[e]], 1);
}

// ---------------- exclusive scan over 100K counters (1 block, 1024 thr) ----------------
__global__ void __launch_bounds__(1024) k_scan() {
    __shared__ int part[1024];
    const int t = threadIdx.x;
    const int CH = (N_ENT + 1023) / 1024;        // 98
    int b = t * CH, e = min(b + CH, N_ENT);
    int s = 0;
    for (int i = b; i < e; i++) s += g_cnt[i];
    part[t] = s;
    __syncthreads();
#pragma unroll
    for (int off = 1; off < 1024; off <<= 1) {
        int v = (t >= off) ? part[t - off] : 0;
        __syncthreads();
        part[t] += v;
        __syncthreads();
    }
    int run = part[t] - s;                       // exclusive
    for (int i = b; i < e; i++) {
        int c = g_cnt[i];
        g_base[i] = run;
        g_cur[i]  = run;
        run += c;
    }
    if (t == 1023) g_base[N_ENT] = N_EDGES;
}

// ---------------- scatter edges into dst-sorted order ----------------
__global__ void k_scatter(const int* __restrict__ src,
                          const int* __restrict__ dst,
                          const int* __restrict__ et) {
    int e = blockIdx.x * blockDim.x + threadIdx.x;
    if (e >= N_EDGES) return;
    int d = dst[e];
    int p = atomicAdd(&g_cur[d], 1);
    s_src[p] = src[e];
    s_dst[p] = d;
    s_et[p]  = et[e];
}

// ---------------- proj[r,n,:] = ent[n,:] @ W_R[r], stored fp16 (FFMA2) ----------------
__global__ void __launch_bounds__(128) k_proj(const float* __restrict__ ent,
                                              const float* __restrict__ WR) {
    __shared__ float Es_t[64][68];   // transposed entity tile [d][row], padded
    __shared__ float Ws[64][64];     // W_R[r] [d][col]
    const int r  = blockIdx.y;
    const int n0 = blockIdx.x * 64;
    const int t  = threadIdx.x;

    const float* Wr = WR + (size_t)r * 4096;
#pragma unroll
    for (int k = 0; k < 8; k++) {
        int q   = t + k * 128;
        int row = q >> 4;
        int c4  = (q & 15) * 4;
        *(float4*)&Ws[row][c4] = *(const float4*)&Wr[row * 64 + c4];
        int gr = n0 + row;
        float4 e4 = make_float4(0.f, 0.f, 0.f, 0.f);
        if (gr < N_ENT) e4 = *(const float4*)&ent[(size_t)gr * 64 + c4];
        Es_t[c4 + 0][row] = e4.x;
        Es_t[c4 + 1][row] = e4.y;
        Es_t[c4 + 2][row] = e4.z;
        Es_t[c4 + 3][row] = e4.w;
    }
    __syncthreads();

    const int rgrp = t & 15;
    const int cgrp = t >> 4;

    ull acc[4][4];
#pragma unroll
    for (int i = 0; i < 4; i++)
#pragma unroll
        for (int j = 0; j < 4; j++) acc[i][j] = pack2(0.f, 0.f);

#pragma unroll 8
    for (int d = 0; d < 64; d++) {
        float4 ev = *(const float4*)&Es_t[d][rgrp * 4];
        ull e0 = pack2(ev.x, ev.x);
        ull e1 = pack2(ev.y, ev.y);
        ull e2 = pack2(ev.z, ev.z);
        ull e3 = pack2(ev.w, ev.w);
        const ull* wrow = (const ull*)&Ws[d][cgrp * 8];
        ull w0 = wrow[0], w1 = wrow[1], w2 = wrow[2], w3 = wrow[3];
        acc[0][0] = ffma2(e0, w0, acc[0][0]); acc[0][1] = ffma2(e0, w1, acc[0][1]);
        acc[0][2] = ffma2(e0, w2, acc[0][2]); acc[0][3] = ffma2(e0, w3, acc[0][3]);
        acc[1][0] = ffma2(e1, w0, acc[1][0]); acc[1][1] = ffma2(e1, w1, acc[1][1]);
        acc[1][2] = ffma2(e1, w2, acc[1][2]); acc[1][3] = ffma2(e1, w3, acc[1][3]);
        acc[2][0] = ffma2(e2, w0, acc[2][0]); acc[2][1] = ffma2(e2, w1, acc[2][1]);
        acc[2][2] = ffma2(e2, w2, acc[2][2]); acc[2][3] = ffma2(e2, w3, acc[2][3]);
        acc[3][0] = ffma2(e3, w0, acc[3][0]); acc[3][1] = ffma2(e3, w1, acc[3][1]);
        acc[3][2] = ffma2(e3, w2, acc[3][2]); acc[3][3] = ffma2(e3, w3, acc[3][3]);
    }

#pragma unroll
    for (int i = 0; i < 4; i++) {
        int gr = n0 + rgrp * 4 + i;
        if (gr < N_ENT) {
            __half2 o[4];
#pragma unroll
            for (int j = 0; j < 4; j++) {
                float2 f = unpack2(acc[i][j]);
                o[j] = __floats2half2_rn(f.x, f.y);
            }
            *(uint4*)&g_proj[((size_t)r * N_ENT + gr) * 64 + cgrp * 8] = *(uint4*)o;
        }
    }
}

// ---------------- per-edge attention on sorted edges (warp per edge) ----------------
__global__ void k_att(const float* __restrict__ rel_emb) {
    int p = blockIdx.x * 8 + (threadIdx.x >> 5);
    if (p >= N_EDGES) return;
    int lane = threadIdx.x & 31;
    int s = s_src[p], d = s_dst[p], r = s_et[p];

    const __half2* gp = (const __half2*)g_proj;
    float2 t2 = __half22float2(gp[((size_t)r * N_ENT + s) * 32 + lane]);
    float2 h2 = __half22float2(gp[((size_t)r * N_ENT + d) * 32 + lane]);
    float2 r2 = *(const float2*)&rel_emb[r * 64 + lane * 2];

    float v = t2.x * ftanh(h2.x + r2.x) + t2.y * ftanh(h2.y + r2.y);
#pragma unroll
    for (int o = 16; o; o >>= 1) v += __shfl_xor_sync(0xFFFFFFFFu, v, o);
    if (lane == 0) s_att[p] = v;
}

// ---------------- per-node edge softmax (warp per node, deterministic) ----------------
__global__ void k_soft() {
    int n = blockIdx.x * 8 + (threadIdx.x >> 5);
    if (n >= N_ENT) return;
    int lane = threadIdx.x & 31;
    int b = g_base[n], e = g_base[n + 1];

    float mx = -3.0e38f;
    for (int i = b + lane; i < e; i += 32) mx = fmaxf(mx, s_att[i]);
#pragma unroll
    for (int o = 16; o; o >>= 1) mx = fmaxf(mx, __shfl_xor_sync(0xFFFFFFFFu, mx, o));

    float sum = 0.f;
    for (int i = b + lane; i < e; i += 32) {
        float ev = __expf(s_att[i] - mx);
        s_att[i] = ev;
        sum += ev;
    }
#pragma unroll
    for (int o = 16; o; o >>= 1) sum += __shfl_xor_sync(0xFFFFFFFFu, sum, o);
    float inv = __fdividef(1.f, sum);

    for (int i = b + lane; i < e; i += 32) s_att[i] *= inv;
}

// ---------------- agg[n] = sum_{edges of n} w * h[src]  (warp per node, no atomics) ----------------
__global__ void k_agg(const float* __restrict__ hsrc, int layer) {
    int n = blockIdx.x * 8 + (threadIdx.x >> 5);
    if (n >= N_ENT) return;
    int lane = threadIdx.x & 31;
    int sub = lane >> 4, l16 = lane & 15;
    int b = g_base[n], e = g_base[n + 1];

    const float* h = layer ? g_h1 : hsrc;
    float* agg     = layer ? g_agg2 : g_agg1;

    float4 acc = make_float4(0.f, 0.f, 0.f, 0.f);
    for (int i = b + sub; i < e; i += 2) {
        float w = s_att[i];
        int s = s_src[i];
        float4 hv = *(const float4*)&h[(size_t)s * 64 + l16 * 4];
        acc.x += w * hv.x; acc.y += w * hv.y;
        acc.z += w * hv.z; acc.w += w * hv.w;
    }
    acc.x += __shfl_xor_sync(0xFFFFFFFFu, acc.x, 16);
    acc.y += __shfl_xor_sync(0xFFFFFFFFu, acc.y, 16);
    acc.z += __shfl_xor_sync(0xFFFFFFFFu, acc.z, 16);
    acc.w += __shfl_xor_sync(0xFFFFFFFFu, acc.w, 16);
    if (sub == 0) *(float4*)&agg[(size_t)n * 64 + l16 * 4] = acc;
}

// ---------------- layer 1 ----------------
__global__ void k_layer1(const float* __restrict__ ent,
                         const float* __restrict__ W0,
                         float* __restrict__ out) {
    __shared__ float Ws[64][64];
    __shared__ float xs[8][64];
    const int tid = threadIdx.x;
#pragma unroll
    for (int k = 0; k < 4; k++) {
        int idx = tid + k * 256;
        int row = idx >> 4, c4 = (idx & 15) * 4;
        *(float4*)&Ws[row][c4] = *(const float4*)&W0[row * 64 + c4];
    }
    __syncthreads();

    const int w = tid >> 5, lane = tid & 31;
    int n = blockIdx.x * 8 + w;
    if (n >= N_ENT) return;

    float2 h2 = *(const float2*)&ent[(size_t)n * 64 + lane * 2];
    float2 a2 = *(const float2*)&g_agg1[(size_t)n * 64 + lane * 2];
    xs[w][lane * 2]     = h2.x * a2.x;
    xs[w][lane * 2 + 1] = h2.y * a2.y;
    __syncwarp();

    float acc0 = 0.f, acc1 = 0.f;
#pragma unroll 8
    for (int d = 0; d < 64; d++) {
        float xd = xs[w][d];
        acc0 += xd * Ws[d][lane];
        acc1 += xd * Ws[d][lane + 32];
    }
    float v0 = (acc0 > 0.f) ? acc0 : 0.01f * acc0;
    float v1 = (acc1 > 0.f) ? acc1 : 0.01f * acc1;
    g_h1[(size_t)n * 64 + lane]      = v0;
    g_h1[(size_t)n * 64 + lane + 32] = v1;

    float sq = v0 * v0 + v1 * v1;
#pragma unroll
    for (int o = 16; o; o >>= 1) sq += __shfl_xor_sync(0xFFFFFFFFu, sq, o);
    float inv = 1.0f / fmaxf(sqrtf(sq), 1e-12f);

    float* orow = out + (size_t)n * 160;
    orow[2 * lane]     = h2.x;
    orow[2 * lane + 1] = h2.y;
    orow[64 + lane]      = v0 * inv;
    orow[64 + lane + 32] = v1 * inv;
}

// ---------------- layer 2 ----------------
__global__ void k_layer2(const float* __restrict__ W1, float* __restrict__ out) {
    __shared__ float Ws[64][32];
    __shared__ float xs[8][64];
    const int tid = threadIdx.x;
#pragma unroll
    for (int k = 0; k < 2; k++) {
        int idx = tid + k * 256;
        int row = idx >> 3, c4 = (idx & 7) * 4;
        *(float4*)&Ws[row][c4] = *(const float4*)&W1[row * 32 + c4];
    }
    __syncthreads();

    const int w = tid >> 5, lane = tid & 31;
    int n = blockIdx.x * 8 + w;
    if (n >= N_ENT) return;

    float2 h2 = *(const float2*)&g_h1[(size_t)n * 64 + lane * 2];
    float2 a2 = *(const float2*)&g_agg2[(size_t)n * 64 + lane * 2];
    xs[w][lane * 2]     = h2.x * a2.x;
    xs[w][lane * 2 + 1] = h2.y * a2.y;
    __syncwarp();

    float acc = 0.f;
#pragma unroll 8
    for (int d = 0; d < 64; d++)
        acc += xs[w][d] * Ws[d][lane];

    float v = (acc > 0.f) ? acc : 0.01f * acc;
    float sq = v * v;
#pragma unroll
    for (int o = 16; o; o >>= 1) sq += __shfl_xor_sync(0xFFFFFFFFu, sq, o);
    float inv = 1.0f / fmaxf(sqrtf(sq), 1e-12f);
    out[(size_t)n * 160 + 128 + lane] = v * inv;
}

extern "C" void kernel_launch(void* const* d_in, const int* in_sizes, int n_in,
                              void* d_out, int out_size) {
    const float* ent = (const float*)d_in[0];
    const float* rel = (const float*)d_in[1];
    const float* WR  = (const float*)d_in[2];
    const float* W0  = (const float*)d_in[3];
    const float* W1  = (const float*)d_in[4];
    const int*   src = (const int*)d_in[5];   // JAX x64 off -> int32
    const int*   dst = (const int*)d_in[6];
    const int*   et  = (const int*)d_in[7];
    float* out = (float*)d_out;

    (void)in_sizes; (void)n_in; (void)out_size;

    const int get = (N_EDGES + 255) / 256;       // thread per edge
    const int geb = (N_EDGES + 7) / 8;           // warp per edge
    const int gnb = (N_ENT + 7) / 8;             // warp per node

    // CSR build
    k_zero<<<(N_ENT + 255) / 256, 256>>>();
    k_hist<<<get, 256>>>(dst);
    k_scan<<<1, 1024>>>();
    k_scatter<<<get, 256>>>(src, dst, et);

    // per-relation projection
    dim3 gp((N_ENT + 63) / 64, N_REL);
    k_proj<<<gp, 128>>>(ent, WR);

    // attention + softmax (deterministic, atomic-free)
    k_att<<<geb, 256>>>(rel);
    k_soft<<<gnb, 256>>>();

    // two GNN layers, atomic-free aggregation
    k_agg<<<gnb, 256>>>(ent, /*layer=*/0);
    k_layer1<<<gnb, 256>>>(ent, W0, out);
    k_agg<<<gnb, 256>>>(ent, /*layer=*/1);
    k_layer2<<<gnb, 256>>>(W1, out);
}

// round 11
// speedup vs baseline: 1.0248x; 1.0248x over previous
#include <cuda_runtime.h>
#include <cuda_fp16.h>

#define N_ENT   100000
#define N_REL   16
#define DIM     64
#define N_EDGES 1600000

typedef unsigned long long ull;

// ---------------- device scratch (no allocs allowed) ----------------
__device__ __half g_proj[(size_t)N_REL * N_ENT * DIM];  // 204.8 MB, fp16
__device__ int   g_cnt[N_ENT];                          // histogram
__device__ int   g_base[N_ENT + 1];                     // CSR row offsets
__device__ int   g_cur[N_ENT];                          // scatter cursors
__device__ int   s_src[N_EDGES];                        // dst-sorted src
__device__ int   s_dst[N_EDGES];                        // dst-sorted dst
__device__ int   s_et[N_EDGES];                         // dst-sorted etype
__device__ float s_att[N_EDGES];                        // att -> softmax weight (sorted)
__device__ float g_h1[N_ENT * DIM];                     // unnormalized layer-1 h

// ---------------- helpers ----------------
__device__ __forceinline__ float ftanh(float x) {       // MUFU.EX2 + RCP, ~1e-6 rel
    x = fminf(fmaxf(x, -15.f), 15.f);
    float e = __expf(2.f * x);
    return __fdividef(e - 1.f, e + 1.f);
}
__device__ __forceinline__ ull pack2(float lo, float hi) {
    ull r; asm("mov.b64 %0, {%1, %2};" : "=l"(r) : "f"(lo), "f"(hi)); return r;
}
__device__ __forceinline__ float2 unpack2(ull v) {
    float lo, hi; asm("mov.b64 {%0, %1}, %2;" : "=f"(lo), "=f"(hi) : "l"(v));
    return make_float2(lo, hi);
}
__device__ __forceinline__ ull ffma2(ull a, ull b, ull c) {
    ull d; asm("fma.rn.f32x2 %0, %1, %2, %3;" : "=l"(d) : "l"(a), "l"(b), "l"(c)); return d;
}

// ---------------- CSR build ----------------
__global__ void k_zero() {
    int i = blockIdx.x * blockDim.x + threadIdx.x;
    if (i < N_ENT) g_cnt[i] = 0;
}
__global__ void k_hist(const int* __restrict__ dst) {
    int e = blockIdx.x * blockDim.x + threadIdx.x;
    if (e < N_EDGES) atomicAdd(&g_cnt[dst[e]], 1);
}
__global__ void __launch_bounds__(1024) k_scan() {
    __shared__ int part[1024];
    const int t = threadIdx.x;
    const int CH = (N_ENT + 1023) / 1024;
    int b = t * CH, e = min(b + CH, N_ENT);
    int s = 0;
    for (int i = b; i < e; i++) s += g_cnt[i];
    part[t] = s;
    __syncthreads();
#pragma unroll
    for (int off = 1; off < 1024; off <<= 1) {
        int v = (t >= off) ? part[t - off] : 0;
        __syncthreads();
        part[t] += v;
        __syncthreads();
    }
    int run = part[t] - s;                       // exclusive
    for (int i = b; i < e; i++) {
        int c = g_cnt[i];
        g_base[i] = run;
        g_cur[i]  = run;
        run += c;
    }
    if (t == 1023) g_base[N_ENT] = N_EDGES;
}
__global__ void k_scatter(const int* __restrict__ src,
                          const int* __restrict__ dst,
                          const int* __restrict__ et) {
    int e = blockIdx.x * blockDim.x + threadIdx.x;
    if (e >= N_EDGES) return;
    int d = dst[e];
    int p = atomicAdd(&g_cur[d], 1);
    s_src[p] = src[e];
    s_dst[p] = d;
    s_et[p]  = et[e];
}

// ---------------- proj[r,n,:] = ent[n,:] @ W_R[r], stored fp16 (FFMA2) ----------------
__global__ void __launch_bounds__(128) k_proj(const float* __restrict__ ent,
                                              const float* __restrict__ WR) {
    __shared__ float Es_t[64][68];
    __shared__ float Ws[64][64];
    const int r  = blockIdx.y;
    const int n0 = blockIdx.x * 64;
    const int t  = threadIdx.x;

    const float* Wr = WR + (size_t)r * 4096;
#pragma unroll
    for (int k = 0; k < 8; k++) {
        int q   = t + k * 128;
        int row = q >> 4;
        int c4  = (q & 15) * 4;
        *(float4*)&Ws[row][c4] = *(const float4*)&Wr[row * 64 + c4];
        int gr = n0 + row;
        float4 e4 = make_float4(0.f, 0.f, 0.f, 0.f);
        if (gr < N_ENT) e4 = *(const float4*)&ent[(size_t)gr * 64 + c4];
        Es_t[c4 + 0][row] = e4.x;
        Es_t[c4 + 1][row] = e4.y;
        Es_t[c4 + 2][row] = e4.z;
        Es_t[c4 + 3][row] = e4.w;
    }
    __syncthreads();

    const int rgrp = t & 15;
    const int cgrp = t >> 4;

    ull acc[4][4];
#pragma unroll
    for (int i = 0; i < 4; i++)
#pragma unroll
        for (int j = 0; j < 4; j++) acc[i][j] = pack2(0.f, 0.f);

#pragma unroll 8
    for (int d = 0; d < 64; d++) {
        float4 ev = *(const float4*)&Es_t[d][rgrp * 4];
        ull e0 = pack2(ev.x, ev.x);
        ull e1 = pack2(ev.y, ev.y);
        ull e2 = pack2(ev.z, ev.z);
        ull e3 = pack2(ev.w, ev.w);
        const ull* wrow = (const ull*)&Ws[d][cgrp * 8];
        ull w0 = wrow[0], w1 = wrow[1], w2 = wrow[2], w3 = wrow[3];
        acc[0][0] = ffma2(e0, w0, acc[0][0]); acc[0][1] = ffma2(e0, w1, acc[0][1]);
        acc[0][2] = ffma2(e0, w2, acc[0][2]); acc[0][3] = ffma2(e0, w3, acc[0][3]);
        acc[1][0] = ffma2(e1, w0, acc[1][0]); acc[1][1] = ffma2(e1, w1, acc[1][1]);
        acc[1][2] = ffma2(e1, w2, acc[1][2]); acc[1][3] = ffma2(e1, w3, acc[1][3]);
        acc[2][0] = ffma2(e2, w0, acc[2][0]); acc[2][1] = ffma2(e2, w1, acc[2][1]);
        acc[2][2] = ffma2(e2, w2, acc[2][2]); acc[2][3] = ffma2(e2, w3, acc[2][3]);
        acc[3][0] = ffma2(e3, w0, acc[3][0]); acc[3][1] = ffma2(e3, w1, acc[3][1]);
        acc[3][2] = ffma2(e3, w2, acc[3][2]); acc[3][3] = ffma2(e3, w3, acc[3][3]);
    }

#pragma unroll
    for (int i = 0; i < 4; i++) {
        int gr = n0 + rgrp * 4 + i;
        if (gr < N_ENT) {
            __half2 o[4];
#pragma unroll
            for (int j = 0; j < 4; j++) {
                float2 f = unpack2(acc[i][j]);
                o[j] = __floats2half2_rn(f.x, f.y);
            }
            *(uint4*)&g_proj[((size_t)r * N_ENT + gr) * 64 + cgrp * 8] = *(uint4*)o;
        }
    }
}

// ---------------- per-edge attention on sorted edges (warp per edge) ----------------
__global__ void k_att(const float* __restrict__ rel_emb) {
    int p = blockIdx.x * 8 + (threadIdx.x >> 5);
    if (p >= N_EDGES) return;
    int lane = threadIdx.x & 31;
    int s = s_src[p], d = s_dst[p], r = s_et[p];

    const __half2* gp = (const __half2*)g_proj;
    float2 t2 = __half22float2(gp[((size_t)r * N_ENT + s) * 32 + lane]);
    float2 h2 = __half22float2(gp[((size_t)r * N_ENT + d) * 32 + lane]);
    float2 r2 = *(const float2*)&rel_emb[r * 64 + lane * 2];

    float v = t2.x * ftanh(h2.x + r2.x) + t2.y * ftanh(h2.y + r2.y);
#pragma unroll
    for (int o = 16; o; o >>= 1) v += __shfl_xor_sync(0xFFFFFFFFu, v, o);
    if (lane == 0) s_att[p] = v;
}

// ---------------- per-node edge softmax (warp per node, deterministic) ----------------
__global__ void k_soft() {
    int n = blockIdx.x * 8 + (threadIdx.x >> 5);
    if (n >= N_ENT) return;
    int lane = threadIdx.x & 31;
    int b = g_base[n], e = g_base[n + 1];

    float mx = -3.0e38f;
    for (int i = b + lane; i < e; i += 32) mx = fmaxf(mx, s_att[i]);
#pragma unroll
    for (int o = 16; o; o >>= 1) mx = fmaxf(mx, __shfl_xor_sync(0xFFFFFFFFu, mx, o));

    float sum = 0.f;
    for (int i = b + lane; i < e; i += 32) {
        float ev = __expf(s_att[i] - mx);
        s_att[i] = ev;
        sum += ev;
    }
#pragma unroll
    for (int o = 16; o; o >>= 1) sum += __shfl_xor_sync(0xFFFFFFFFu, sum, o);
    float inv = __fdividef(1.f, sum);

    for (int i = b + lane; i < e; i += 32) s_att[i] *= inv;
}

// ---------------- unrolled gather-reduce: agg[64] for node n (warp-cooperative) ----------------
// subwarp (16 lanes) owns alternate edges; unroll 2 -> 4 outstanding 256B gathers/warp.
// Returns this lane's float4 chunk of agg (all 32 lanes valid: lanes 0-15 & 16-31 mirror).
__device__ __forceinline__ float4 gather_agg(const float* __restrict__ h, int b, int e,
                                             int sub, int l16) {
    float4 a0 = make_float4(0.f, 0.f, 0.f, 0.f);
    float4 a1 = make_float4(0.f, 0.f, 0.f, 0.f);
    int i = b + sub;
    for (; i + 2 < e; i += 4) {
        float w0 = s_att[i],     w1 = s_att[i + 2];
        int   s0 = s_src[i],     s1 = s_src[i + 2];
        float4 v0 = *(const float4*)&h[(size_t)s0 * 64 + l16 * 4];
        float4 v1 = *(const float4*)&h[(size_t)s1 * 64 + l16 * 4];
        a0.x += w0 * v0.x; a0.y += w0 * v0.y; a0.z += w0 * v0.z; a0.w += w0 * v0.w;
        a1.x += w1 * v1.x; a1.y += w1 * v1.y; a1.z += w1 * v1.z; a1.w += w1 * v1.w;
    }
    if (i < e) {
        float w0 = s_att[i];
        float4 v0 = *(const float4*)&h[(size_t)s_src[i] * 64 + l16 * 4];
        a0.x += w0 * v0.x; a0.y += w0 * v0.y; a0.z += w0 * v0.z; a0.w += w0 * v0.w;
    }
    a0.x += a1.x; a0.y += a1.y; a0.z += a1.z; a0.w += a1.w;
    a0.x += __shfl_xor_sync(0xFFFFFFFFu, a0.x, 16);
    a0.y += __shfl_xor_sync(0xFFFFFFFFu, a0.y, 16);
    a0.z += __shfl_xor_sync(0xFFFFFFFFu, a0.z, 16);
    a0.w += __shfl_xor_sync(0xFFFFFFFFu, a0.w, 16);
    return a0;   // all lanes hold the combined chunk for dims [l16*4, l16*4+4)
}

// ---------------- fused layer 1: agg + (h*agg)@W0 + lrelu + l2norm + out ----------------
__global__ void __launch_bounds__(256) k_fused1(const float* __restrict__ ent,
                                                const float* __restrict__ W0,
                                                float* __restrict__ out) {
    __shared__ float Ws[64][64];
    __shared__ float xs[8][64];
    const int tid = threadIdx.x;
#pragma unroll
    for (int k = 0; k < 4; k++) {
        int idx = tid + k * 256;
        int row = idx >> 4, c4 = (idx & 15) * 4;
        *(float4*)&Ws[row][c4] = *(const float4*)&W0[row * 64 + c4];
    }
    __syncthreads();

    const int w = tid >> 5, lane = tid & 31;
    const int sub = lane >> 4, l16 = lane & 15;
    int n = blockIdx.x * 8 + w;
    if (n >= N_ENT) return;

    float4 agg = gather_agg(ent, g_base[n], g_base[n + 1], sub, l16);

    // x = h0[n] * agg  (this lane's 4-dim chunk), stash row in smem
    float4 h4 = *(const float4*)&ent[(size_t)n * 64 + l16 * 4];
    if (sub == 0)
        *(float4*)&xs[w][l16 * 4] = make_float4(h4.x * agg.x, h4.y * agg.y,
                                                h4.z * agg.z, h4.w * agg.w);
    __syncwarp();

    float acc0 = 0.f, acc1 = 0.f;
#pragma unroll 8
    for (int d = 0; d < 64; d++) {
        float xd = xs[w][d];
        acc0 += xd * Ws[d][lane];
        acc1 += xd * Ws[d][lane + 32];
    }
    float v0 = (acc0 > 0.f) ? acc0 : 0.01f * acc0;
    float v1 = (acc1 > 0.f) ? acc1 : 0.01f * acc1;
    g_h1[(size_t)n * 64 + lane]      = v0;
    g_h1[(size_t)n * 64 + lane + 32] = v1;

    float sq = v0 * v0 + v1 * v1;
#pragma unroll
    for (int o = 16; o; o >>= 1) sq += __shfl_xor_sync(0xFFFFFFFFu, sq, o);
    float inv = 1.0f / fmaxf(sqrtf(sq), 1e-12f);

    float* orow = out + (size_t)n * 160;
    float2 h2 = *(const float2*)&ent[(size_t)n * 64 + lane * 2];
    orow[2 * lane]     = h2.x;          // cache[0] = raw entity embed
    orow[2 * lane + 1] = h2.y;
    orow[64 + lane]      = v0 * inv;    // cache[1] = l2norm(h1)
    orow[64 + lane + 32] = v1 * inv;
}

// ---------------- fused layer 2: agg + (h1*agg)@W1 + lrelu + l2norm + out ----------------
__global__ void __launch_bounds__(256) k_fused2(const float* __restrict__ W1,
                                                float* __restrict__ out) {
    __shared__ float Ws[64][32];
    __shared__ float xs[8][64];
    const int tid = threadIdx.x;
#pragma unroll
    for (int k = 0; k < 2; k++) {
        int idx = tid + k * 256;
        int row = idx >> 3, c4 = (idx & 7) * 4;
        *(float4*)&Ws[row][c4] = *(const float4*)&W1[row * 32 + c4];
    }
    __syncthreads();

    const int w = tid >> 5, lane = tid & 31;
    const int sub = lane >> 4, l16 = lane & 15;
    int n = blockIdx.x * 8 + w;
    if (n >= N_ENT) return;

    float4 agg = gather_agg(g_h1, g_base[n], g_base[n + 1], sub, l16);

    float4 h4 = *(const float4*)&g_h1[(size_t)n * 64 + l16 * 4];
    if (sub == 0)
        *(float4*)&xs[w][l16 * 4] = make_float4(h4.x * agg.x, h4.y * agg.y,
                                                h4.z * agg.z, h4.w * agg.w);
    __syncwarp();

    float acc = 0.f;
#pragma unroll 8
    for (int d = 0; d < 64; d++)
        acc += xs[w][d] * Ws[d][lane];

    float v = (acc > 0.f) ? acc : 0.01f * acc;
    float sq = v * v;
#pragma unroll
    for (int o = 16; o; o >>= 1) sq += __shfl_xor_sync(0xFFFFFFFFu, sq, o);
    float inv = 1.0f / fmaxf(sqrtf(sq), 1e-12f);
    out[(size_t)n * 160 + 128 + lane] = v * inv;
}

extern "C" void kernel_launch(void* const* d_in, const int* in_sizes, int n_in,
                              void* d_out, int out_size) {
    const float* ent = (const float*)d_in[0];
    const float* rel = (const float*)d_in[1];
    const float* WR  = (const float*)d_in[2];
    const float* W0  = (const float*)d_in[3];
    const float* W1  = (const float*)d_in[4];
    const int*   src = (const int*)d_in[5];   // JAX x64 off -> int32
    const int*   dst = (const int*)d_in[6];
    const int*   et  = (const int*)d_in[7];
    float* out = (float*)d_out;

    (void)in_sizes; (void)n_in; (void)out_size;

    const int get = (N_EDGES + 255) / 256;       // thread per edge
    const int geb = (N_EDGES + 7) / 8;           // warp per edge
    const int gnb = (N_ENT + 7) / 8;             // warp per node

    // CSR build
    k_zero<<<(N_ENT + 255) / 256, 256>>>();
    k_hist<<<get, 256>>>(dst);
    k_scan<<<1, 1024>>>();
    k_scatter<<<get, 256>>>(src, dst, et);

    // per-relation projection
    dim3 gp((N_ENT + 63) / 64, N_REL);
    k_proj<<<gp, 128>>>(ent, WR);

    // attention + softmax (deterministic, atomic-free)
    k_att<<<geb, 256>>>(rel);
    k_soft<<<gnb, 256>>>();

    // two fused GNN layers (gather-reduce + matvec + norm + output)
    k_fused1<<<gnb, 256>>>(ent, W0, out);
    k_fused2<<<gnb, 256>>>(W1, out);
}

// round 12
// speedup vs baseline: 1.5137x; 1.4771x over previous
#include <cuda_runtime.h>
#include <cuda_fp16.h>

#define N_ENT   100000
#define N_REL   16
#define DIM     64
#define N_EDGES 1600000

typedef unsigned long long ull;

// ---------------- device scratch (no allocs allowed) ----------------
__device__ __half g_proj[(size_t)N_REL * N_ENT * DIM];  // 204.8 MB, fp16
__device__ int   g_cnt[N_ENT];                          // histogram (memset to 0)
__device__ int   g_base[N_ENT + 1];                     // CSR row offsets
__device__ int   g_cur[N_ENT];                          // scatter cursors
__device__ int   s_src[N_EDGES];                        // dst-sorted src
__device__ int   s_dst[N_EDGES];                        // dst-sorted dst
__device__ int   s_et[N_EDGES];                         // dst-sorted etype
__device__ float s_att[N_EDGES];                        // att -> softmax weight (sorted)
__device__ float g_h1[N_ENT * DIM];                     // unnormalized layer-1 h

// ---------------- helpers ----------------
__device__ __forceinline__ float ftanh(float x) {       // MUFU.EX2 + RCP, ~1e-6 rel
    x = fminf(fmaxf(x, -15.f), 15.f);
    float e = __expf(2.f * x);
    return __fdividef(e - 1.f, e + 1.f);
}

// ---------------- CSR build ----------------
__global__ void k_hist(const int* __restrict__ dst) {
    int e = blockIdx.x * blockDim.x + threadIdx.x;
    if (e < N_EDGES) atomicAdd(&g_cnt[dst[e]], 1);
}
__global__ void __launch_bounds__(1024) k_scan() {
    __shared__ int part[1024];
    const int t = threadIdx.x;
    const int CH = (N_ENT + 1023) / 1024;
    int b = t * CH, e = min(b + CH, N_ENT);
    int s = 0;
    for (int i = b; i < e; i++) s += g_cnt[i];
    part[t] = s;
    __syncthreads();
#pragma unroll
    for (int off = 1; off < 1024; off <<= 1) {
        int v = (t >= off) ? part[t - off] : 0;
        __syncthreads();
        part[t] += v;
        __syncthreads();
    }
    int run = part[t] - s;                       // exclusive
    for (int i = b; i < e; i++) {
        int c = g_cnt[i];
        g_base[i] = run;
        g_cur[i]  = run;
        run += c;
    }
    if (t == 1023) g_base[N_ENT] = N_EDGES;
}
__global__ void k_scatter(const int* __restrict__ src,
                          const int* __restrict__ dst,
                          const int* __restrict__ et) {
    int e = blockIdx.x * blockDim.x + threadIdx.x;
    if (e >= N_EDGES) return;
    int d = dst[e];
    int p = atomicAdd(&g_cur[d], 1);
    s_src[p] = src[e];
    s_dst[p] = d;
    s_et[p]  = et[e];
}

// ---------------- proj[r,n,:] = ent[n,:] @ W_R[r], HMMA m16n8k16, fp16 out ----------------
// block 256 thr (8 warps), tile 128 nodes x 64 cols, one relation.
// smem rows padded to 72 halves (144B = 9*16B): frag LDS.32 conflict-free.
__global__ void __launch_bounds__(256) k_proj(const float* __restrict__ ent,
                                              const float* __restrict__ WR) {
    __shared__ __half A_s[128 * 72];    // ent tile fp16 [row][72]; reused for output
    __shared__ __half W_t[64 * 72];     // W transposed: W_t[e][d] = W[d][e]
    const int r  = blockIdx.y;
    const int n0 = blockIdx.x * 128;
    const int t  = threadIdx.x;

    // stage A (fp32 -> fp16): 128x16 float4 slots
#pragma unroll
    for (int k = 0; k < 8; k++) {
        int q = t + k * 256;
        int row = q >> 4, c4 = (q & 15) * 4;
        int gr = n0 + row;
        float4 v = make_float4(0.f, 0.f, 0.f, 0.f);
        if (gr < N_ENT) v = *(const float4*)&ent[(size_t)gr * 64 + c4];
        __half2* dp = (__half2*)&A_s[row * 72 + c4];
        dp[0] = __floats2half2_rn(v.x, v.y);
        dp[1] = __floats2half2_rn(v.z, v.w);
    }
    // stage W transposed (fp32 -> fp16): 64x16 float4 slots
    const float* Wr = WR + (size_t)r * 4096;
#pragma unroll
    for (int k = 0; k < 4; k++) {
        int q = t + k * 256;
        int d = q >> 4, e4 = (q & 15) * 4;
        float4 v = *(const float4*)&Wr[d * 64 + e4];
        W_t[(e4 + 0) * 72 + d] = __float2half_rn(v.x);
        W_t[(e4 + 1) * 72 + d] = __float2half_rn(v.y);
        W_t[(e4 + 2) * 72 + d] = __float2half_rn(v.z);
        W_t[(e4 + 3) * 72 + d] = __float2half_rn(v.w);
    }
    __syncthreads();

    const int w    = t >> 5, lane = t & 31;
    const int qr   = lane >> 2;          // 0..7
    const int qc   = (lane & 3) * 2;     // 0,2,4,6
    const int m0   = w * 16;

    float acc[8][4];
#pragma unroll
    for (int i = 0; i < 8; i++)
#pragma unroll
        for (int j = 0; j < 4; j++) acc[i][j] = 0.f;

#pragma unroll
    for (int ks = 0; ks < 4; ks++) {
        int kb = ks * 16;
        unsigned a0 = *(const unsigned*)&A_s[(m0 + qr)     * 72 + kb + qc];
        unsigned a1 = *(const unsigned*)&A_s[(m0 + qr + 8) * 72 + kb + qc];
        unsigned a2 = *(const unsigned*)&A_s[(m0 + qr)     * 72 + kb + qc + 8];
        unsigned a3 = *(const unsigned*)&A_s[(m0 + qr + 8) * 72 + kb + qc + 8];
#pragma unroll
        for (int nt = 0; nt < 8; nt++) {
            int nb = nt * 8 + qr;
            unsigned b0 = *(const unsigned*)&W_t[nb * 72 + kb + qc];
            unsigned b1 = *(const unsigned*)&W_t[nb * 72 + kb + qc + 8];
            asm volatile(
                "mma.sync.aligned.m16n8k16.row.col.f32.f16.f16.f32 "
                "{%0,%1,%2,%3}, {%4,%5,%6,%7}, {%8,%9}, {%0,%1,%2,%3};"
                : "+f"(acc[nt][0]), "+f"(acc[nt][1]), "+f"(acc[nt][2]), "+f"(acc[nt][3])
                : "r"(a0), "r"(a1), "r"(a2), "r"(a3), "r"(b0), "r"(b1));
        }
    }
    __syncthreads();   // done reading A_s; reuse as fp16 output staging

    // D frag layout: d0,d1 = D[qr][qc..qc+1]; d2,d3 = D[qr+8][qc..qc+1]
#pragma unroll
    for (int nt = 0; nt < 8; nt++) {
        int col = nt * 8 + qc;
        *(__half2*)&A_s[(m0 + qr)     * 72 + col] = __floats2half2_rn(acc[nt][0], acc[nt][1]);
        *(__half2*)&A_s[(m0 + qr + 8) * 72 + col] = __floats2half2_rn(acc[nt][2], acc[nt][3]);
    }
    __syncthreads();

    // coalesced writeout: 128 rows x 8 uint4 (16B) chunks
#pragma unroll
    for (int k = 0; k < 4; k++) {
        int q = t + k * 256;
        int row = q >> 3, c8 = (q & 7) * 8;
        int gr = n0 + row;
        if (gr < N_ENT)
            *(uint4*)&g_proj[((size_t)r * N_ENT + gr) * 64 + c8] =
                *(const uint4*)&A_s[row * 72 + c8];
    }
}

// ---------------- per-edge attention (2 edges/warp: 16 lanes x uint2 = full row) ----------------
__global__ void k_att(const float* __restrict__ rel_emb) {
    int p = blockIdx.x * 16 + (threadIdx.x >> 4);
    if (p >= N_EDGES) return;
    int l = threadIdx.x & 15;
    int s = s_src[p], d = s_dst[p], r = s_et[p];

    const uint2* gp = (const uint2*)g_proj;     // 4 halves per uint2, 16 per row
    uint2 tu = __ldg(&gp[((size_t)r * N_ENT + s) * 16 + l]);
    uint2 hu = __ldg(&gp[((size_t)r * N_ENT + d) * 16 + l]);
    float4 rv = *(const float4*)&rel_emb[r * 64 + l * 4];

    float2 ta = __half22float2(*(__half2*)&tu.x);
    float2 tb = __half22float2(*(__half2*)&tu.y);
    float2 ha = __half22float2(*(__half2*)&hu.x);
    float2 hb = __half22float2(*(__half2*)&hu.y);

    float v = ta.x * ftanh(ha.x + rv.x) + ta.y * ftanh(ha.y + rv.y)
            + tb.x * ftanh(hb.x + rv.z) + tb.y * ftanh(hb.y + rv.w);
#pragma unroll
    for (int o = 8; o; o >>= 1) v += __shfl_xor_sync(0xFFFFFFFFu, v, o);
    if (l == 0) s_att[p] = v;
}

// ---------------- per-node edge softmax (warp per node, deterministic) ----------------
__global__ void k_soft() {
    int n = blockIdx.x * 8 + (threadIdx.x >> 5);
    if (n >= N_ENT) return;
    int lane = threadIdx.x & 31;
    int b = g_base[n], e = g_base[n + 1];

    float mx = -3.0e38f;
    for (int i = b + lane; i < e; i += 32) mx = fmaxf(mx, s_att[i]);
#pragma unroll
    for (int o = 16; o; o >>= 1) mx = fmaxf(mx, __shfl_xor_sync(0xFFFFFFFFu, mx, o));

    float sum = 0.f;
    for (int i = b + lane; i < e; i += 32) {
        float ev = __expf(s_att[i] - mx);
        s_att[i] = ev;
        sum += ev;
    }
#pragma unroll
    for (int o = 16; o; o >>= 1) sum += __shfl_xor_sync(0xFFFFFFFFu, sum, o);
    float inv = __fdividef(1.f, sum);

    for (int i = b + lane; i < e; i += 32) s_att[i] *= inv;
}

// ---------------- gather-reduce (unroll 4: 8 outstanding 256B gathers/warp) ----------------
__device__ __forceinline__ float4 gather_agg(const float* __restrict__ h, int b, int e,
                                             int sub, int l16) {
    float4 a0 = make_float4(0.f, 0.f, 0.f, 0.f);
    float4 a1 = make_float4(0.f, 0.f, 0.f, 0.f);
    float4 a2 = make_float4(0.f, 0.f, 0.f, 0.f);
    float4 a3 = make_float4(0.f, 0.f, 0.f, 0.f);
    int i = b + sub;
    for (; i + 6 < e; i += 8) {
        float w0 = s_att[i],     w1 = s_att[i + 2];
        float w2 = s_att[i + 4], w3 = s_att[i + 6];
        int   q0 = s_src[i],     q1 = s_src[i + 2];
        int   q2 = s_src[i + 4], q3 = s_src[i + 6];
        float4 v0 = *(const float4*)&h[(size_t)q0 * 64 + l16 * 4];
        float4 v1 = *(const float4*)&h[(size_t)q1 * 64 + l16 * 4];
        float4 v2 = *(const float4*)&h[(size_t)q2 * 64 + l16 * 4];
        float4 v3 = *(const float4*)&h[(size_t)q3 * 64 + l16 * 4];
        a0.x += w0 * v0.x; a0.y += w0 * v0.y; a0.z += w0 * v0.z; a0.w += w0 * v0.w;
        a1.x += w1 * v1.x; a1.y += w1 * v1.y; a1.z += w1 * v1.z; a1.w += w1 * v1.w;
        a2.x += w2 * v2.x; a2.y += w2 * v2.y; a2.z += w2 * v2.z; a2.w += w2 * v2.w;
        a3.x += w3 * v3.x; a3.y += w3 * v3.y; a3.z += w3 * v3.z; a3.w += w3 * v3.w;
    }
    for (; i < e; i += 2) {
        float w0 = s_att[i];
        float4 v0 = *(const float4*)&h[(size_t)s_src[i] * 64 + l16 * 4];
        a0.x += w0 * v0.x; a0.y += w0 * v0.y; a0.z += w0 * v0.z; a0.w += w0 * v0.w;
    }
    a0.x += a1.x + a2.x + a3.x;
    a0.y += a1.y + a2.y + a3.y;
    a0.z += a1.z + a2.z + a3.z;
    a0.w += a1.w + a2.w + a3.w;
    a0.x += __shfl_xor_sync(0xFFFFFFFFu, a0.x, 16);
    a0.y += __shfl_xor_sync(0xFFFFFFFFu, a0.y, 16);
    a0.z += __shfl_xor_sync(0xFFFFFFFFu, a0.z, 16);
    a0.w += __shfl_xor_sync(0xFFFFFFFFu, a0.w, 16);
    return a0;
}

// ---------------- fused layer 1: agg + (h*agg)@W0 + lrelu + l2norm + out ----------------
__global__ void __launch_bounds__(256) k_fused1(const float* __restrict__ ent,
                                                const float* __restrict__ W0,
                                                float* __restrict__ out) {
    __shared__ float Ws[64][64];
    __shared__ float xs[8][64];
    const int tid = threadIdx.x;
#pragma unroll
    for (int k = 0; k < 4; k++) {
        int idx = tid + k * 256;
        int row = idx >> 4, c4 = (idx & 15) * 4;
        *(float4*)&Ws[row][c4] = *(const float4*)&W0[row * 64 + c4];
    }
    __syncthreads();

    const int w = tid >> 5, lane = tid & 31;
    const int sub = lane >> 4, l16 = lane & 15;
    int n = blockIdx.x * 8 + w;
    if (n >= N_ENT) return;

    float4 agg = gather_agg(ent, g_base[n], g_base[n + 1], sub, l16);

    float4 h4 = *(const float4*)&ent[(size_t)n * 64 + l16 * 4];
    if (sub == 0)
        *(float4*)&xs[w][l16 * 4] = make_float4(h4.x * agg.x, h4.y * agg.y,
                                                h4.z * agg.z, h4.w * agg.w);
    __syncwarp();

    float acc0 = 0.f, acc1 = 0.f;
#pragma unroll 8
    for (int d = 0; d < 64; d++) {
        float xd = xs[w][d];
        acc0 += xd * Ws[d][lane];
        acc1 += xd * Ws[d][lane + 32];
    }
    float v0 = (acc0 > 0.f) ? acc0 : 0.01f * acc0;
    float v1 = (acc1 > 0.f) ? acc1 : 0.01f * acc1;
    g_h1[(size_t)n * 64 + lane]      = v0;
    g_h1[(size_t)n * 64 + lane + 32] = v1;

    float sq = v0 * v0 + v1 * v1;
#pragma unroll
    for (int o = 16; o; o >>= 1) sq += __shfl_xor_sync(0xFFFFFFFFu, sq, o);
    float inv = 1.0f / fmaxf(sqrtf(sq), 1e-12f);

    float* orow = out + (size_t)n * 160;
    float2 h2 = *(const float2*)&ent[(size_t)n * 64 + lane * 2];
    orow[2 * lane]     = h2.x;          // cache[0] = raw entity embed
    orow[2 * lane + 1] = h2.y;
    orow[64 + lane]      = v0 * inv;    // cache[1] = l2norm(h1)
    orow[64 + lane + 32] = v1 * inv;
}

// ---------------- fused layer 2: agg + (h1*agg)@W1 + lrelu + l2norm + out ----------------
__global__ void __launch_bounds__(256) k_fused2(const float* __restrict__ W1,
                                                float* __restrict__ out) {
    __shared__ float Ws[64][32];
    __shared__ float xs[8][64];
    const int tid = threadIdx.x;
#pragma unroll
    for (int k = 0; k < 2; k++) {
        int idx = tid + k * 256;
        int row = idx >> 3, c4 = (idx & 7) * 4;
        *(float4*)&Ws[row][c4] = *(const float4*)&W1[row * 32 + c4];
    }
    __syncthreads();

    const int w = tid >> 5, lane = tid & 31;
    const int sub = lane >> 4, l16 = lane & 15;
    int n = blockIdx.x * 8 + w;
    if (n >= N_ENT) return;

    float4 agg = gather_agg(g_h1, g_base[n], g_base[n + 1], sub, l16);

    float4 h4 = *(const float4*)&g_h1[(size_t)n * 64 + l16 * 4];
    if (sub == 0)
        *(float4*)&xs[w][l16 * 4] = make_float4(h4.x * agg.x, h4.y * agg.y,
                                                h4.z * agg.z, h4.w * agg.w);
    __syncwarp();

    float acc = 0.f;
#pragma unroll 8
    for (int d = 0; d < 64; d++)
        acc += xs[w][d] * Ws[d][lane];

    float v = (acc > 0.f) ? acc : 0.01f * acc;
    float sq = v * v;
#pragma unroll
    for (int o = 16; o; o >>= 1) sq += __shfl_xor_sync(0xFFFFFFFFu, sq, o);
    float inv = 1.0f / fmaxf(sqrtf(sq), 1e-12f);
    out[(size_t)n * 160 + 128 + lane] = v * inv;
}

extern "C" void kernel_launch(void* const* d_in, const int* in_sizes, int n_in,
                              void* d_out, int out_size) {
    const float* ent = (const float*)d_in[0];
    const float* rel = (const float*)d_in[1];
    const float* WR  = (const float*)d_in[2];
    const float* W0  = (const float*)d_in[3];
    const float* W1  = (const float*)d_in[4];
    const int*   src = (const int*)d_in[5];   // JAX x64 off -> int32
    const int*   dst = (const int*)d_in[6];
    const int*   et  = (const int*)d_in[7];
    float* out = (float*)d_out;

    (void)in_sizes; (void)n_in; (void)out_size;

    const int get = (N_EDGES + 255) / 256;       // thread per edge
    const int gnb = (N_ENT + 7) / 8;             // warp per node

    // zero histogram via memset node (keeps k_proj as the 4th kernel launch)
    void* cnt_ptr = nullptr;
    cudaGetSymbolAddress(&cnt_ptr, g_cnt);
    cudaMemsetAsync(cnt_ptr, 0, N_ENT * sizeof(int));

    // CSR build (3 kernels)
    k_hist<<<get, 256>>>(dst);
    k_scan<<<1, 1024>>>();
    k_scatter<<<get, 256>>>(src, dst, et);

    // per-relation projection, HMMA (4th kernel -> profiled)
    dim3 gp((N_ENT + 127) / 128, N_REL);
    k_proj<<<gp, 256>>>(ent, WR);

    // attention + softmax (deterministic, atomic-free)
    k_att<<<(N_EDGES + 15) / 16, 256>>>(rel);
    k_soft<<<gnb, 256>>>();

    // two fused GNN layers
    k_fused1<<<gnb, 256>>>(ent, W0, out);
    k_fused2<<<gnb, 256>>>(W1, out);
}

// round 14
// speedup vs baseline: 1.6697x; 1.1030x over previous
#include <cuda_runtime.h>
#include <cuda_fp16.h>
#include <cstdint>

#define N_ENT   100000
#define N_REL   16
#define DIM     64
#define N_EDGES 1600000

// ---------------- device scratch (no allocs allowed) ----------------
__device__ __half g_proj[(size_t)N_REL * N_ENT * DIM];  // 204.8 MB, fp16
__device__ __half g_ent16[N_ENT * DIM];                 // fp16 mirror of entity_embed
__device__ __half g_h16[N_ENT * DIM];                   // fp16 mirror of h1
__device__ float g_att[N_EDGES];                        // raw att, original edge order
__device__ int   g_cnt[N_ENT];                          // histogram (memset to 0)
__device__ int   g_base[N_ENT + 1];                     // CSR row offsets
__device__ int   g_cur[N_ENT];                          // scatter cursors
__device__ int   s_src[N_EDGES];                        // dst-sorted src
__device__ float s_att[N_EDGES];                        // dst-sorted att -> softmax w
__device__ float g_h1[N_ENT * DIM];                     // unnormalized layer-1 h (fp32)

// ---------------- helpers ----------------
__device__ __forceinline__ float tanhf_a(float x) {     // MUFU.TANH, ~2^-11
    float y; asm("tanh.approx.f32 %0, %1;" : "=f"(y) : "f"(x)); return y;
}

// ---------------- CSR build ----------------
__global__ void k_hist(const int* __restrict__ dst) {
    int e = blockIdx.x * blockDim.x + threadIdx.x;
    if (e < N_EDGES) atomicAdd(&g_cnt[dst[e]], 1);
}
__global__ void __launch_bounds__(1024) k_scan() {
    __shared__ int part[1024];
    const int t = threadIdx.x;
    const int CH = (N_ENT + 1023) / 1024;
    int b = t * CH, e = min(b + CH, N_ENT);
    int s = 0;
    for (int i = b; i < e; i++) s += g_cnt[i];
    part[t] = s;
    __syncthreads();
#pragma unroll
    for (int off = 1; off < 1024; off <<= 1) {
        int v = (t >= off) ? part[t - off] : 0;
        __syncthreads();
        part[t] += v;
        __syncthreads();
    }
    int run = part[t] - s;                       // exclusive
    for (int i = b; i < e; i++) {
        int c = g_cnt[i];
        g_base[i] = run;
        g_cur[i]  = run;
        run += c;
    }
    if (t == 1023) g_base[N_ENT] = N_EDGES;
}
// scatter src + att into dst-sorted order (2 random 4B stores/edge)
__global__ void k_scatter(const int* __restrict__ src,
                          const int* __restrict__ dst) {
    int e = blockIdx.x * blockDim.x + threadIdx.x;
    if (e >= N_EDGES) return;
    int d = dst[e];
    int p = atomicAdd(&g_cur[d], 1);
    s_src[p] = src[e];
    s_att[p] = g_att[e];
}

// ---------------- ent fp32 -> fp16 mirror ----------------
__global__ void k_conv(const float* __restrict__ ent) {
    int i = blockIdx.x * blockDim.x + threadIdx.x;   // float4 index
    if (i >= N_ENT * 16) return;
    float4 v = ((const float4*)ent)[i];
    __half2* o = (__half2*)g_ent16;
    o[i * 2]     = __floats2half2_rn(v.x, v.y);
    o[i * 2 + 1] = __floats2half2_rn(v.z, v.w);
}

// ---------------- proj[r,n,:] = ent[n,:] @ W_R[r], HMMA + ldmatrix ----------------
// block 256 thr (8 warps), tile 128 nodes x 64 cols, one relation.
// smem rows padded to 72 halves (144B): LDSM conflict-free.
__global__ void __launch_bounds__(256) k_proj(const float* __restrict__ ent,
                                              const float* __restrict__ WR) {
    __shared__ __half A_s[128 * 72];    // ent tile fp16 [row][72]; reused for output
    __shared__ __half W_t[64 * 72];     // W transposed: W_t[e][d] = W[d][e]
    const int r  = blockIdx.y;
    const int n0 = blockIdx.x * 128;
    const int t  = threadIdx.x;

    // stage A (fp32 -> fp16)
#pragma unroll
    for (int k = 0; k < 8; k++) {
        int q = t + k * 256;
        int row = q >> 4, c4 = (q & 15) * 4;
        int gr = n0 + row;
        float4 v = make_float4(0.f, 0.f, 0.f, 0.f);
        if (gr < N_ENT) v = *(const float4*)&ent[(size_t)gr * 64 + c4];
        __half2* dp = (__half2*)&A_s[row * 72 + c4];
        dp[0] = __floats2half2_rn(v.x, v.y);
        dp[1] = __floats2half2_rn(v.z, v.w);
    }
    // stage W transposed (fp32 -> fp16)
    const float* Wr = WR + (size_t)r * 4096;
#pragma unroll
    for (int k = 0; k < 4; k++) {
        int q = t + k * 256;
        int d = q >> 4, e4 = (q & 15) * 4;
        float4 v = *(const float4*)&Wr[d * 64 + e4];
        W_t[(e4 + 0) * 72 + d] = __float2half_rn(v.x);
        W_t[(e4 + 1) * 72 + d] = __float2half_rn(v.y);
        W_t[(e4 + 2) * 72 + d] = __float2half_rn(v.z);
        W_t[(e4 + 3) * 72 + d] = __float2half_rn(v.w);
    }
    __syncthreads();

    const int w    = t >> 5, lane = t & 31;
    const int qr   = lane >> 2;          // 0..7
    const int qc   = (lane & 3) * 2;     // 0,2,4,6
    const int m0   = w * 16;
    const int lrow = lane & 7;

    // ldmatrix lane addresses
    uint32_t A_base = (uint32_t)__cvta_generic_to_shared(A_s);
    uint32_t W_base = (uint32_t)__cvta_generic_to_shared(W_t);
    uint32_t aptr = A_base + (uint32_t)(((m0 + lrow + ((lane >> 3) & 1) * 8) * 72
                                        + (lane >> 4) * 8) * 2);
    uint32_t bptr = W_base + (uint32_t)((lrow * 72 + ((lane >> 3) & 1) * 8) * 2);

    float acc[8][4];
#pragma unroll
    for (int i = 0; i < 8; i++)
#pragma unroll
        for (int j = 0; j < 4; j++) acc[i][j] = 0.f;

#pragma unroll
    for (int ks = 0; ks < 4; ks++) {
        int kb = ks * 16;
        unsigned a0, a1, a2, a3;
        asm volatile("ldmatrix.sync.aligned.m8n8.x4.shared.b16 {%0,%1,%2,%3}, [%4];"
                     : "=r"(a0), "=r"(a1), "=r"(a2), "=r"(a3)
                     : "r"(aptr + kb * 2));
#pragma unroll
        for (int nt = 0; nt < 8; nt++) {
            unsigned b0, b1;
            asm volatile("ldmatrix.sync.aligned.m8n8.x2.shared.b16 {%0,%1}, [%2];"
                         : "=r"(b0), "=r"(b1)
                         : "r"(bptr + (nt * 8 * 72 + kb) * 2));
            asm volatile(
                "mma.sync.aligned.m16n8k16.row.col.f32.f16.f16.f32 "
                "{%0,%1,%2,%3}, {%4,%5,%6,%7}, {%8,%9}, {%0,%1,%2,%3};"
                : "+f"(acc[nt][0]), "+f"(acc[nt][1]), "+f"(acc[nt][2]), "+f"(acc[nt][3])
                : "r"(a0), "r"(a1), "r"(a2), "r"(a3), "r"(b0), "r"(b1));
        }
    }
    __syncthreads();   // done reading A_s; reuse as fp16 output staging

#pragma unroll
    for (int nt = 0; nt < 8; nt++) {
        int col = nt * 8 + qc;
        *(__half2*)&A_s[(m0 + qr)     * 72 + col] = __floats2half2_rn(acc[nt][0], acc[nt][1]);
        *(__half2*)&A_s[(m0 + qr + 8) * 72 + col] = __floats2half2_rn(acc[nt][2], acc[nt][3]);
    }
    __syncthreads();

#pragma unroll
    for (int k = 0; k < 4; k++) {
        int q = t + k * 256;
        int row = q >> 3, c8 = (q & 7) * 8;
        int gr = n0 + row;
        if (gr < N_ENT)
            *(uint4*)&g_proj[((size_t)r * N_ENT + gr) * 64 + c8] =
                *(const uint4*)&A_s[row * 72 + c8];
    }
}

// ---------------- per-edge attention, original edge order (4 edges/warp) ----------------
__global__ void k_att(const float* __restrict__ rel_emb,
                      const int* __restrict__ src,
                      const int* __restrict__ dst,
                      const int* __restrict__ et) {
    int p = blockIdx.x * 32 + (threadIdx.x >> 3);
    if (p >= N_EDGES) return;
    int l = threadIdx.x & 7;
    int s = src[p], d = dst[p], r = et[p];

    const uint4* gp = (const uint4*)g_proj;     // 8 halves per uint4
    uint4 tu = __ldg(&gp[((size_t)r * N_ENT + s) * 8 + l]);
    uint4 hu = __ldg(&gp[((size_t)r * N_ENT + d) * 8 + l]);
    float4 rv0 = *(const float4*)&rel_emb[r * 64 + l * 8];
    float4 rv1 = *(const float4*)&rel_emb[r * 64 + l * 8 + 4];

    float2 t0 = __half22float2(*(__half2*)&tu.x);
    float2 t1 = __half22float2(*(__half2*)&tu.y);
    float2 t2 = __half22float2(*(__half2*)&tu.z);
    float2 t3 = __half22float2(*(__half2*)&tu.w);
    float2 h0 = __half22float2(*(__half2*)&hu.x);
    float2 h1 = __half22float2(*(__half2*)&hu.y);
    float2 h2 = __half22float2(*(__half2*)&hu.z);
    float2 h3 = __half22float2(*(__half2*)&hu.w);

    float v = t0.x * tanhf_a(h0.x + rv0.x) + t0.y * tanhf_a(h0.y + rv0.y)
            + t1.x * tanhf_a(h1.x + rv0.z) + t1.y * tanhf_a(h1.y + rv0.w)
            + t2.x * tanhf_a(h2.x + rv1.x) + t2.y * tanhf_a(h2.y + rv1.y)
            + t3.x * tanhf_a(h3.x + rv1.z) + t3.y * tanhf_a(h3.y + rv1.w);
#pragma unroll
    for (int o = 4; o; o >>= 1) v += __shfl_xor_sync(0xFFFFFFFFu, v, o);
    if (l == 0) g_att[p] = v;
}

// ---------------- per-node edge softmax (warp per node, deterministic) ----------------
__global__ void k_soft() {
    int n = blockIdx.x * 8 + (threadIdx.x >> 5);
    if (n >= N_ENT) return;
    int lane = threadIdx.x & 31;
    int b = g_base[n], e = g_base[n + 1];

    float mx = -3.0e38f;
    for (int i = b + lane; i < e; i += 32) mx = fmaxf(mx, s_att[i]);
#pragma unroll
    for (int o = 16; o; o >>= 1) mx = fmaxf(mx, __shfl_xor_sync(0xFFFFFFFFu, mx, o));

    float sum = 0.f;
    for (int i = b + lane; i < e; i += 32) {
        float ev = __expf(s_att[i] - mx);
        s_att[i] = ev;
        sum += ev;
    }
#pragma unroll
    for (int o = 16; o; o >>= 1) sum += __shfl_xor_sync(0xFFFFFFFFu, sum, o);
    float inv = __fdividef(1.f, sum);

    for (int i = b + lane; i < e; i += 32) s_att[i] *= inv;
}

// ---------------- fp16 gather-reduce (unroll 4, 128B per row) ----------------
__device__ __forceinline__ float4 gather_agg16(const __half* __restrict__ ht,
                                               int b, int e, int sub, int l16) {
    const uint2* hp = (const uint2*)ht;          // 4 halves per uint2, 16 per row
    float4 a0 = make_float4(0.f, 0.f, 0.f, 0.f);
    float4 a1 = make_float4(0.f, 0.f, 0.f, 0.f);
    float4 a2 = make_float4(0.f, 0.f, 0.f, 0.f);
    float4 a3 = make_float4(0.f, 0.f, 0.f, 0.f);
    int i = b + sub;
    for (; i + 6 < e; i += 8) {
        float w0 = s_att[i],     w1 = s_att[i + 2];
        float w2 = s_att[i + 4], w3 = s_att[i + 6];
        uint2 u0 = __ldg(&hp[(size_t)s_src[i]     * 16 + l16]);
        uint2 u1 = __ldg(&hp[(size_t)s_src[i + 2] * 16 + l16]);
        uint2 u2 = __ldg(&hp[(size_t)s_src[i + 4] * 16 + l16]);
        uint2 u3 = __ldg(&hp[(size_t)s_src[i + 6] * 16 + l16]);
        float2 p0 = __half22float2(*(__half2*)&u0.x), q0 = __half22float2(*(__half2*)&u0.y);
        float2 p1 = __half22float2(*(__half2*)&u1.x), q1 = __half22float2(*(__half2*)&u1.y);
        float2 p2 = __half22float2(*(__half2*)&u2.x), q2 = __half22float2(*(__half2*)&u2.y);
        float2 p3 = __half22float2(*(__half2*)&u3.x), q3 = __half22float2(*(__half2*)&u3.y);
        a0.x += w0 * p0.x; a0.y += w0 * p0.y; a0.z += w0 * q0.x; a0.w += w0 * q0.y;
        a1.x += w1 * p1.x; a1.y += w1 * p1.y; a1.z += w1 * q1.x; a1.w += w1 * q1.y;
        a2.x += w2 * p2.x; a2.y += w2 * p2.y; a2.z += w2 * q2.x; a2.w += w2 * q2.y;
        a3.x += w3 * p3.x; a3.y += w3 * p3.y; a3.z += w3 * q3.x; a3.w += w3 * q3.y;
    }
    for (; i < e; i += 2) {
        float w0 = s_att[i];
        uint2 u0 = __ldg(&hp[(size_t)s_src[i] * 16 + l16]);
        float2 p0 = __half22float2(*(__half2*)&u0.x), q0 = __half22float2(*(__half2*)&u0.y);
        a0.x += w0 * p0.x; a0.y += w0 * p0.y; a0.z += w0 * q0.x; a0.w += w0 * q0.y;
    }
    a0.x += a1.x + a2.x + a3.x;
    a0.y += a1.y + a2.y + a3.y;
    a0.z += a1.z + a2.z + a3.z;
    a0.w += a1.w + a2.w + a3.w;
    a0.x += __shfl_xor_sync(0xFFFFFFFFu, a0.x, 16);
    a0.y += __shfl_xor_sync(0xFFFFFFFFu, a0.y, 16);
    a0.z += __shfl_xor_sync(0xFFFFFFFFu, a0.z, 16);
    a0.w += __shfl_xor_sync(0xFFFFFFFFu, a0.w, 16);
    return a0;
}

// ---------------- fused layer 1 ----------------
__global__ void __launch_bounds__(256) k_fused1(const float* __restrict__ ent,
                                                const float* __restrict__ W0,
                                                float* __restrict__ out) {
    __shared__ float Ws[64][64];
    __shared__ float xs[8][64];
    const int tid = threadIdx.x;
#pragma unroll
    for (int k = 0; k < 4; k++) {
        int idx = tid + k * 256;
        int row = idx >> 4, c4 = (idx & 15) * 4;
        *(float4*)&Ws[row][c4] = *(const float4*)&W0[row * 64 + c4];
    }
    __syncthreads();

    const int w = tid >> 5, lane = tid & 31;
    const int sub = lane >> 4, l16 = lane & 15;
    int n = blockIdx.x * 8 + w;
    if (n >= N_ENT) return;

    float4 agg = gather_agg16(g_ent16, g_base[n], g_base[n + 1], sub, l16);

    float4 h4 = *(const float4*)&ent[(size_t)n * 64 + l16 * 4];
    if (sub == 0)
        *(float4*)&xs[w][l16 * 4] = make_float4(h4.x * agg.x, h4.y * agg.y,
                                                h4.z * agg.z, h4.w * agg.w);
    __syncwarp();

    float acc0 = 0.f, acc1 = 0.f;
#pragma unroll 8
    for (int d = 0; d < 64; d++) {
        float xd = xs[w][d];
        acc0 += xd * Ws[d][lane];
        acc1 += xd * Ws[d][lane + 32];
    }
    float v0 = (acc0 > 0.f) ? acc0 : 0.01f * acc0;
    float v1 = (acc1 > 0.f) ? acc1 : 0.01f * acc1;
    g_h1[(size_t)n * 64 + lane]      = v0;
    g_h1[(size_t)n * 64 + lane + 32] = v1;
    g_h16[(size_t)n * 64 + lane]      = __float2half_rn(v0);
    g_h16[(size_t)n * 64 + lane + 32] = __float2half_rn(v1);

    float sq = v0 * v0 + v1 * v1;
#pragma unroll
    for (int o = 16; o; o >>= 1) sq += __shfl_xor_sync(0xFFFFFFFFu, sq, o);
    float inv = 1.0f / fmaxf(sqrtf(sq), 1e-12f);

    float* orow = out + (size_t)n * 160;
    float2 h2 = *(const float2*)&ent[(size_t)n * 64 + lane * 2];
    orow[2 * lane]     = h2.x;          // cache[0] = raw entity embed
    orow[2 * lane + 1] = h2.y;
    orow[64 + lane]      = v0 * inv;    // cache[1] = l2norm(h1)
    orow[64 + lane + 32] = v1 * inv;
}

// ---------------- fused layer 2 ----------------
__global__ void __launch_bounds__(256) k_fused2(const float* __restrict__ W1,
                                                float* __restrict__ out) {
    __shared__ float Ws[64][32];
    __shared__ float xs[8][64];
    const int tid = threadIdx.x;
#pragma unroll
    for (int k = 0; k < 2; k++) {
        int idx = tid + k * 256;
        int row = idx >> 3, c4 = (idx & 7) * 4;
        *(float4*)&Ws[row][c4] = *(const float4*)&W1[row * 32 + c4];
    }
    __syncthreads();

    const int w = tid >> 5, lane = tid & 31;
    const int sub = lane >> 4, l16 = lane & 15;
    int n = blockIdx.x * 8 + w;
    if (n >= N_ENT) return;

    float4 agg = gather_agg16(g_h16, g_base[n], g_base[n + 1], sub, l16);

    float4 h4 = *(const float4*)&g_h1[(size_t)n * 64 + l16 * 4];
    if (sub == 0)
        *(float4*)&xs[w][l16 * 4] = make_float4(h4.x * agg.x, h4.y * agg.y,
                                                h4.z * agg.z, h4.w * agg.w);
    __syncwarp();

    float acc = 0.f;
#pragma unroll 8
    for (int d = 0; d < 64; d++)
        acc += xs[w][d] * Ws[d][lane];

    float v = (acc > 0.f) ? acc : 0.01f * acc;
    float sq = v * v;
#pragma unroll
    for (int o = 16; o; o >>= 1) sq += __shfl_xor_sync(0xFFFFFFFFu, sq, o);
    float inv = 1.0f / fmaxf(sqrtf(sq), 1e-12f);
    out[(size_t)n * 160 + 128 + lane] = v * inv;
}

extern "C" void kernel_launch(void* const* d_in, const int* in_sizes, int n_in,
                              void* d_out, int out_size) {
    const float* ent = (const float*)d_in[0];
    const float* rel = (const float*)d_in[1];
    const float* WR  = (const float*)d_in[2];
    const float* W0  = (const float*)d_in[3];
    const float* W1  = (const float*)d_in[4];
    const int*   src = (const int*)d_in[5];   // JAX x64 off -> int32
    const int*   dst = (const int*)d_in[6];
    const int*   et  = (const int*)d_in[7];
    float* out = (float*)d_out;

    (void)in_sizes; (void)n_in; (void)out_size;

    const int get = (N_EDGES + 255) / 256;       // thread per edge
    const int gnb = (N_ENT + 7) / 8;             // warp per node

    void* cnt_ptr = nullptr;
    cudaGetSymbolAddress(&cnt_ptr, g_cnt);
    cudaMemsetAsync(cnt_ptr, 0, N_ENT * sizeof(int));

    // launch order keeps k_att as the 4th kernel (profiled next round)
    k_hist<<<get, 256>>>(dst);                               // 1
    k_conv<<<(N_ENT * 16 + 255) / 256, 256>>>(ent);          // 2
    dim3 gp((N_ENT + 127) / 128, N_REL);
    k_proj<<<gp, 256>>>(ent, WR);                            // 3
    k_att<<<(N_EDGES + 31) / 32, 256>>>(rel, src, dst, et);  // 4  <- profiled
    k_scan<<<1, 1024>>>();                                   // 5
    k_scatter<<<get, 256>>>(src, dst);                       // 6
    k_soft<<<gnb, 256>>>();                                  // 7
    k_fused1<<<gnb, 256>>>(ent, W0, out);                    // 8
    k_fused2<<<gnb, 256>>>(W1, out);                         // 9
}

// round 15
// speedup vs baseline: 1.7294x; 1.0358x over previous
#include <cuda_runtime.h>
#include <cuda_fp16.h>
#include <cstdint>

#define N_ENT   100000
#define N_REL   16
#define DIM     64
#define N_EDGES 1600000

// ---------------- device scratch (no allocs allowed) ----------------
__device__ __half g_proj[(size_t)N_REL * N_ENT * DIM];  // 204.8 MB, fp16
__device__ __half g_ent16[N_ENT * DIM];                 // fp16 mirror of entity_embed
__device__ __half g_h16[N_ENT * DIM];                   // fp16 h1 (unnormalized)
__device__ int   g_cnt[N_ENT];                          // histogram (memset to 0)
__device__ int   g_base[N_ENT + 1];                     // CSR row offsets
__device__ int   g_cur[N_ENT];                          // scatter cursors
__device__ int   s_src[N_EDGES];                        // dst-sorted src
__device__ float s_att[N_EDGES];                        // dst-sorted att -> softmax w

// ---------------- helpers ----------------
__device__ __forceinline__ float tanhf_a(float x) {     // MUFU.TANH, ~2^-11
    float y; asm("tanh.approx.f32 %0, %1;" : "=f"(y) : "f"(x)); return y;
}

// ---------------- CSR build ----------------
__global__ void k_hist(const int* __restrict__ dst) {
    int e = blockIdx.x * blockDim.x + threadIdx.x;
    if (e < N_EDGES) atomicAdd(&g_cnt[dst[e]], 1);
}
__global__ void __launch_bounds__(1024) k_scan() {
    __shared__ int part[1024];
    const int t = threadIdx.x;
    const int CH = (N_ENT + 1023) / 1024;
    int b = t * CH, e = min(b + CH, N_ENT);
    int s = 0;
    for (int i = b; i < e; i++) s += g_cnt[i];
    part[t] = s;
    __syncthreads();
#pragma unroll
    for (int off = 1; off < 1024; off <<= 1) {
        int v = (t >= off) ? part[t - off] : 0;
        __syncthreads();
        part[t] += v;
        __syncthreads();
    }
    int run = part[t] - s;                       // exclusive
    for (int i = b; i < e; i++) {
        int c = g_cnt[i];
        g_base[i] = run;
        g_cur[i]  = run;
        run += c;
    }
    if (t == 1023) g_base[N_ENT] = N_EDGES;
}

// ---------------- proj: all 16 relations per 128-node tile (HMMA + ldmatrix) ----------------
// A staged fp16 once (also written to g_ent16); W_R looped from L2.
// smem rows padded to 72 halves (144B): LDSM conflict-free.
__global__ void __launch_bounds__(256) k_proj(const float* __restrict__ ent,
                                              const float* __restrict__ WR) {
    __shared__ __half A_s[128 * 72];
    __shared__ __half W_t[64 * 72];     // W transposed: W_t[e][d] = W[d][e]
    __shared__ __half D_s[128 * 72];    // output staging
    const int n0 = blockIdx.x * 128;
    const int t  = threadIdx.x;

    // stage A (fp32 -> fp16), and mirror to g_ent16
#pragma unroll
    for (int k = 0; k < 8; k++) {
        int q = t + k * 256;
        int row = q >> 4, c4 = (q & 15) * 4;
        int gr = n0 + row;
        float4 v = make_float4(0.f, 0.f, 0.f, 0.f);
        if (gr < N_ENT) v = *(const float4*)&ent[(size_t)gr * 64 + c4];
        __half2 h0 = __floats2half2_rn(v.x, v.y);
        __half2 h1 = __floats2half2_rn(v.z, v.w);
        __half2* dp = (__half2*)&A_s[row * 72 + c4];
        dp[0] = h0;
        dp[1] = h1;
        if (gr < N_ENT) {
            uint2 u;
            u.x = *(unsigned*)&h0;
            u.y = *(unsigned*)&h1;
            *(uint2*)&g_ent16[(size_t)gr * 64 + c4] = u;
        }
    }
    __syncthreads();

    const int w    = t >> 5, lane = t & 31;
    const int qr   = lane >> 2;          // 0..7
    const int qc   = (lane & 3) * 2;     // 0,2,4,6
    const int m0   = w * 16;
    const int lrow = lane & 7;

    uint32_t A_base = (uint32_t)__cvta_generic_to_shared(A_s);
    uint32_t W_base = (uint32_t)__cvta_generic_to_shared(W_t);
    uint32_t aptr = A_base + (uint32_t)(((m0 + lrow + ((lane >> 3) & 1) * 8) * 72
                                        + (lane >> 4) * 8) * 2);
    uint32_t bptr = W_base + (uint32_t)((lrow * 72 + ((lane >> 3) & 1) * 8) * 2);

    for (int r = 0; r < N_REL; r++) {
        // stage W_r transposed (fp32 -> fp16)
        const float* Wr = WR + (size_t)r * 4096;
#pragma unroll
        for (int k = 0; k < 4; k++) {
            int q = t + k * 256;
            int d = q >> 4, e4 = (q & 15) * 4;
            float4 v = *(const float4*)&Wr[d * 64 + e4];
            W_t[(e4 + 0) * 72 + d] = __float2half_rn(v.x);
            W_t[(e4 + 1) * 72 + d] = __float2half_rn(v.y);
            W_t[(e4 + 2) * 72 + d] = __float2half_rn(v.z);
            W_t[(e4 + 3) * 72 + d] = __float2half_rn(v.w);
        }
        __syncthreads();

        float acc[8][4];
#pragma unroll
        for (int i = 0; i < 8; i++)
#pragma unroll
            for (int j = 0; j < 4; j++) acc[i][j] = 0.f;

#pragma unroll
        for (int ks = 0; ks < 4; ks++) {
            int kb = ks * 16;
            unsigned a0, a1, a2, a3;
            asm volatile("ldmatrix.sync.aligned.m8n8.x4.shared.b16 {%0,%1,%2,%3}, [%4];"
                         : "=r"(a0), "=r"(a1), "=r"(a2), "=r"(a3)
                         : "r"(aptr + kb * 2));
#pragma unroll
            for (int nt = 0; nt < 8; nt++) {
                unsigned b0, b1;
                asm volatile("ldmatrix.sync.aligned.m8n8.x2.shared.b16 {%0,%1}, [%2];"
                             : "=r"(b0), "=r"(b1)
                             : "r"(bptr + (nt * 8 * 72 + kb) * 2));
                asm volatile(
                    "mma.sync.aligned.m16n8k16.row.col.f32.f16.f16.f32 "
                    "{%0,%1,%2,%3}, {%4,%5,%6,%7}, {%8,%9}, {%0,%1,%2,%3};"
                    : "+f"(acc[nt][0]), "+f"(acc[nt][1]), "+f"(acc[nt][2]), "+f"(acc[nt][3])
                    : "r"(a0), "r"(a1), "r"(a2), "r"(a3), "r"(b0), "r"(b1));
            }
        }

        // D frags -> staging
#pragma unroll
        for (int nt = 0; nt < 8; nt++) {
            int col = nt * 8 + qc;
            *(__half2*)&D_s[(m0 + qr)     * 72 + col] = __floats2half2_rn(acc[nt][0], acc[nt][1]);
            *(__half2*)&D_s[(m0 + qr + 8) * 72 + col] = __floats2half2_rn(acc[nt][2], acc[nt][3]);
        }
        __syncthreads();

        // coalesced writeout
#pragma unroll
        for (int k = 0; k < 4; k++) {
            int q = t + k * 256;
            int row = q >> 3, c8 = (q & 7) * 8;
            int gr = n0 + row;
            if (gr < N_ENT)
                *(uint4*)&g_proj[((size_t)r * N_ENT + gr) * 64 + c8] =
                    *(const uint4*)&D_s[row * 72 + c8];
        }
        __syncthreads();   // W_t / D_s reused next relation
    }
}

// ---------------- attention + inline scatter (4 edges/warp, 8 lanes each) ----------------
__global__ void k_att(const float* __restrict__ rel_emb,
                      const int* __restrict__ src,
                      const int* __restrict__ dst,
                      const int* __restrict__ et) {
    int p = blockIdx.x * 32 + (threadIdx.x >> 3);
    if (p >= N_EDGES) return;
    int l = threadIdx.x & 7;
    int s = src[p], d = dst[p], r = et[p];

    const uint4* gp = (const uint4*)g_proj;     // 8 halves per uint4
    uint4 tu = __ldg(&gp[((size_t)r * N_ENT + s) * 8 + l]);
    uint4 hu = __ldg(&gp[((size_t)r * N_ENT + d) * 8 + l]);
    float4 rv0 = *(const float4*)&rel_emb[r * 64 + l * 8];
    float4 rv1 = *(const float4*)&rel_emb[r * 64 + l * 8 + 4];

    float2 t0 = __half22float2(*(__half2*)&tu.x);
    float2 t1 = __half22float2(*(__half2*)&tu.y);
    float2 t2 = __half22float2(*(__half2*)&tu.z);
    float2 t3 = __half22float2(*(__half2*)&tu.w);
    float2 h0 = __half22float2(*(__half2*)&hu.x);
    float2 h1 = __half22float2(*(__half2*)&hu.y);
    float2 h2 = __half22float2(*(__half2*)&hu.z);
    float2 h3 = __half22float2(*(__half2*)&hu.w);

    float v = t0.x * tanhf_a(h0.x + rv0.x) + t0.y * tanhf_a(h0.y + rv0.y)
            + t1.x * tanhf_a(h1.x + rv0.z) + t1.y * tanhf_a(h1.y + rv0.w)
            + t2.x * tanhf_a(h2.x + rv1.x) + t2.y * tanhf_a(h2.y + rv1.y)
            + t3.x * tanhf_a(h3.x + rv1.z) + t3.y * tanhf_a(h3.y + rv1.w);
#pragma unroll
    for (int o = 4; o; o >>= 1) v += __shfl_xor_sync(0xFFFFFFFFu, v, o);
    if (l == 0) {
        int pos = atomicAdd(&g_cur[d], 1);
        s_src[pos] = s;
        s_att[pos] = v;
    }
}

// ---------------- per-node edge softmax (warp per node, deterministic order) ----------------
__global__ void k_soft() {
    int n = blockIdx.x * 8 + (threadIdx.x >> 5);
    if (n >= N_ENT) return;
    int lane = threadIdx.x & 31;
    int b = g_base[n], e = g_base[n + 1];

    float mx = -3.0e38f;
    for (int i = b + lane; i < e; i += 32) mx = fmaxf(mx, s_att[i]);
#pragma unroll
    for (int o = 16; o; o >>= 1) mx = fmaxf(mx, __shfl_xor_sync(0xFFFFFFFFu, mx, o));

    float sum = 0.f;
    for (int i = b + lane; i < e; i += 32) {
        float ev = __expf(s_att[i] - mx);
        s_att[i] = ev;
        sum += ev;
    }
#pragma unroll
    for (int o = 16; o; o >>= 1) sum += __shfl_xor_sync(0xFFFFFFFFu, sum, o);
    float inv = __fdividef(1.f, sum);

    for (int i = b + lane; i < e; i += 32) s_att[i] *= inv;
}

// ---------------- fp16 gather-reduce (unroll 4, 128B per row) ----------------
__device__ __forceinline__ float4 gather_agg16(const __half* __restrict__ ht,
                                               int b, int e, int sub, int l16) {
    const uint2* hp = (const uint2*)ht;          // 4 halves per uint2, 16 per row
    float4 a0 = make_float4(0.f, 0.f, 0.f, 0.f);
    float4 a1 = make_float4(0.f, 0.f, 0.f, 0.f);
    float4 a2 = make_float4(0.f, 0.f, 0.f, 0.f);
    float4 a3 = make_float4(0.f, 0.f, 0.f, 0.f);
    int i = b + sub;
    for (; i + 6 < e; i += 8) {
        float w0 = s_att[i],     w1 = s_att[i + 2];
        float w2 = s_att[i + 4], w3 = s_att[i + 6];
        uint2 u0 = __ldg(&hp[(size_t)s_src[i]     * 16 + l16]);
        uint2 u1 = __ldg(&hp[(size_t)s_src[i + 2] * 16 + l16]);
        uint2 u2 = __ldg(&hp[(size_t)s_src[i + 4] * 16 + l16]);
        uint2 u3 = __ldg(&hp[(size_t)s_src[i + 6] * 16 + l16]);
        float2 p0 = __half22float2(*(__half2*)&u0.x), q0 = __half22float2(*(__half2*)&u0.y);
        float2 p1 = __half22float2(*(__half2*)&u1.x), q1 = __half22float2(*(__half2*)&u1.y);
        float2 p2 = __half22float2(*(__half2*)&u2.x), q2 = __half22float2(*(__half2*)&u2.y);
        float2 p3 = __half22float2(*(__half2*)&u3.x), q3 = __half22float2(*(__half2*)&u3.y);
        a0.x += w0 * p0.x; a0.y += w0 * p0.y; a0.z += w0 * q0.x; a0.w += w0 * q0.y;
        a1.x += w1 * p1.x; a1.y += w1 * p1.y; a1.z += w1 * q1.x; a1.w += w1 * q1.y;
        a2.x += w2 * p2.x; a2.y += w2 * p2.y; a2.z += w2 * q2.x; a2.w += w2 * q2.y;
        a3.x += w3 * p3.x; a3.y += w3 * p3.y; a3.z += w3 * q3.x; a3.w += w3 * q3.y;
    }
    for (; i < e; i += 2) {
        float w0 = s_att[i];
        uint2 u0 = __ldg(&hp[(size_t)s_src[i] * 16 + l16]);
        float2 p0 = __half22float2(*(__half2*)&u0.x), q0 = __half22float2(*(__half2*)&u0.y);
        a0.x += w0 * p0.x; a0.y += w0 * p0.y; a0.z += w0 * q0.x; a0.w += w0 * q0.y;
    }
    a0.x += a1.x + a2.x + a3.x;
    a0.y += a1.y + a2.y + a3.y;
    a0.z += a1.z + a2.z + a3.z;
    a0.w += a1.w + a2.w + a3.w;
    a0.x += __shfl_xor_sync(0xFFFFFFFFu, a0.x, 16);
    a0.y += __shfl_xor_sync(0xFFFFFFFFu, a0.y, 16);
    a0.z += __shfl_xor_sync(0xFFFFFFFFu, a0.z, 16);
    a0.w += __shfl_xor_sync(0xFFFFFFFFu, a0.w, 16);
    return a0;
}

// ---------------- fused layer 1 ----------------
__global__ void __launch_bounds__(256) k_fused1(const float* __restrict__ ent,
                                                const float* __restrict__ W0,
                                                float* __restrict__ out) {
    __shared__ float Ws[64][64];
    __shared__ float xs[8][64];
    const int tid = threadIdx.x;
#pragma unroll
    for (int k = 0; k < 4; k++) {
        int idx = tid + k * 256;
        int row = idx >> 4, c4 = (idx & 15) * 4;
        *(float4*)&Ws[row][c4] = *(const float4*)&W0[row * 64 + c4];
    }
    __syncthreads();

    const int w = tid >> 5, lane = tid & 31;
    const int sub = lane >> 4, l16 = lane & 15;
    int n = blockIdx.x * 8 + w;
    if (n >= N_ENT) return;

    float4 agg = gather_agg16(g_ent16, g_base[n], g_base[n + 1], sub, l16);

    float4 h4 = *(const float4*)&ent[(size_t)n * 64 + l16 * 4];
    if (sub == 0)
        *(float4*)&xs[w][l16 * 4] = make_float4(h4.x * agg.x, h4.y * agg.y,
                                                h4.z * agg.z, h4.w * agg.w);
    __syncwarp();

    float acc0 = 0.f, acc1 = 0.f;
#pragma unroll 8
    for (int d = 0; d < 64; d++) {
        float xd = xs[w][d];
        acc0 += xd * Ws[d][lane];
        acc1 += xd * Ws[d][lane + 32];
    }
    float v0 = (acc0 > 0.f) ? acc0 : 0.01f * acc0;
    float v1 = (acc1 > 0.f) ? acc1 : 0.01f * acc1;
    g_h16[(size_t)n * 64 + lane]      = __float2half_rn(v0);
    g_h16[(size_t)n * 64 + lane + 32] = __float2half_rn(v1);

    float sq = v0 * v0 + v1 * v1;
#pragma unroll
    for (int o = 16; o; o >>= 1) sq += __shfl_xor_sync(0xFFFFFFFFu, sq, o);
    float inv = 1.0f / fmaxf(sqrtf(sq), 1e-12f);

    float* orow = out + (size_t)n * 160;
    float2 h2 = *(const float2*)&ent[(size_t)n * 64 + lane * 2];
    orow[2 * lane]     = h2.x;          // cache[0] = raw entity embed
    orow[2 * lane + 1] = h2.y;
    orow[64 + lane]      = v0 * inv;    // cache[1] = l2norm(h1)
    orow[64 + lane + 32] = v1 * inv;
}

// ---------------- fused layer 2 ----------------
__global__ void __launch_bounds__(256) k_fused2(const float* __restrict__ W1,
                                                float* __restrict__ out) {
    __shared__ float Ws[64][32];
    __shared__ float xs[8][64];
    const int tid = threadIdx.x;
#pragma unroll
    for (int k = 0; k < 2; k++) {
        int idx = tid + k * 256;
        int row = idx >> 3, c4 = (idx & 7) * 4;
        *(float4*)&Ws[row][c4] = *(const float4*)&W1[row * 32 + c4];
    }
    __syncthreads();

    const int w = tid >> 5, lane = tid & 31;
    const int sub = lane >> 4, l16 = lane & 15;
    int n = blockIdx.x * 8 + w;
    if (n >= N_ENT) return;

    float4 agg = gather_agg16(g_h16, g_base[n], g_base[n + 1], sub, l16);

    // local h1 term from fp16 mirror
    uint2 hu = *(const uint2*)&g_h16[(size_t)n * 64 + l16 * 4];
    float2 ha = __half22float2(*(__half2*)&hu.x);
    float2 hb = __half22float2(*(__half2*)&hu.y);
    if (sub == 0)
        *(float4*)&xs[w][l16 * 4] = make_float4(ha.x * agg.x, ha.y * agg.y,
                                                hb.x * agg.z, hb.y * agg.w);
    __syncwarp();

    float acc = 0.f;
#pragma unroll 8
    for (int d = 0; d < 64; d++)
        acc += xs[w][d] * Ws[d][lane];

    float v = (acc > 0.f) ? acc : 0.01f * acc;
    float sq = v * v;
#pragma unroll
    for (int o = 16; o; o >>= 1) sq += __shfl_xor_sync(0xFFFFFFFFu, sq, o);
    float inv = 1.0f / fmaxf(sqrtf(sq), 1e-12f);
    out[(size_t)n * 160 + 128 + lane] = v * inv;
}

extern "C" void kernel_launch(void* const* d_in, const int* in_sizes, int n_in,
                              void* d_out, int out_size) {
    const float* ent = (const float*)d_in[0];
    const float* rel = (const float*)d_in[1];
    const float* WR  = (const float*)d_in[2];
    const float* W0  = (const float*)d_in[3];
    const float* W1  = (const float*)d_in[4];
    const int*   src = (const int*)d_in[5];   // JAX x64 off -> int32
    const int*   dst = (const int*)d_in[6];
    const int*   et  = (const int*)d_in[7];
    float* out = (float*)d_out;

    (void)in_sizes; (void)n_in; (void)out_size;

    const int get = (N_EDGES + 255) / 256;       // thread per edge
    const int gnb = (N_ENT + 7) / 8;             // warp per node

    void* cnt_ptr = nullptr;
    cudaGetSymbolAddress(&cnt_ptr, g_cnt);
    cudaMemsetAsync(cnt_ptr, 0, N_ENT * sizeof(int));

    k_hist<<<get, 256>>>(dst);                               // 1
    k_scan<<<1, 1024>>>();                                   // 2
    k_proj<<<(N_ENT + 127) / 128, 256>>>(ent, WR);           // 3
    k_att<<<(N_EDGES + 31) / 32, 256>>>(rel, src, dst, et);  // 4  <- profiled
    k_soft<<<gnb, 256>>>();                                  // 5
    k_fused1<<<gnb, 256>>>(ent, W0, out);                    // 6
    k_fused2<<<gnb, 256>>>(W1, out);                         // 7
}